// round 15
// baseline (speedup 1.0000x reference)
#include <cuda_runtime.h>
#include <cstdint>

#define HID 128
#define NN 50000
#define NE 800000
#define NG 64
#define NL 2

#define SCAN_B 512
#define SCAN_BLOCKS ((NN + SCAN_B - 1) / SCAN_B)   // 98

// ---------------- scratch (static device allocations) ----------------
__device__ __align__(16) float g_M[NN * HID];    // x + aggregation (gemm input)
__device__ __align__(16) float g_R[NN * HID];    // layer raw output
__device__ __align__(16) uint32_t g_Wf[4 * 32768]; // fragment-major hi/lo weights
__device__ __align__(16) float g_T[76 * HID];    // layer-0 message table relu(nemb[i]+eemb[a])
__device__ int g_cnt[NN];                        // zeroed by scan1 of the PREVIOUS call
__device__ int g_off[NN + 1];
__device__ int g_cur[NN];
__device__ int g_bsum[SCAN_BLOCKS];
__device__ int g_list[NE];                       // (x_idx[src]<<2)|attr  (layer 0)
__device__ int g_list2[NE];                      // (src<<2)|attr         (layer 1)
__device__ double g_sum0[HID], g_sumsq0[HID];    // layer-0 BN stats
__device__ double g_sum1[HID], g_sumsq1[HID];    // layer-1 BN stats

__device__ __forceinline__ uint32_t f2tf32(float v) {
    uint32_t o;
    asm("cvt.rna.tf32.f32 %0, %1;" : "=r"(o) : "f"(v));
    return o;
}
__device__ __forceinline__ void split_tf32(float v, uint32_t& h, uint32_t& l) {
    h = f2tf32(v);
    l = f2tf32(v - __uint_as_float(h));
}

#define MMA_TF32(d, a, b) \
    asm volatile("mma.sync.aligned.m16n8k8.row.col.f32.tf32.tf32.f32 " \
        "{%0,%1,%2,%3}, {%4,%5,%6,%7}, {%8,%9}, {%0,%1,%2,%3};" \
        : "+f"((d)[0]), "+f"((d)[1]), "+f"((d)[2]), "+f"((d)[3]) \
        : "r"((a)[0]), "r"((a)[1]), "r"((a)[2]), "r"((a)[3]), \
          "r"((b)[0]), "r"((b)[1]))

// scale/shift from stats (identical math to the old finalize kernel)
__device__ __forceinline__ void scale_shift(const double* __restrict__ sum,
                                            const double* __restrict__ sumsq,
                                            const float* __restrict__ gw,
                                            const float* __restrict__ bw,
                                            int c, float& sc, float& sh) {
    double mu = sum[c] / (double)NN;
    double var = sumsq[c] / (double)NN - mu * mu;
    sc = (float)((double)gw[c] * rsqrt(var + 1e-5));
    sh = bw[c] - (float)mu * sc;
}

// ---------------- prep: weights, msg table, hist, zero stats+out (one kernel) ----------------
__global__ void prep_kernel(const float* __restrict__ W1, const float* __restrict__ W2,
                            const float* __restrict__ nemb, const float* __restrict__ eemb,
                            const int* __restrict__ ei, float* __restrict__ out) {
    int i = blockIdx.x * blockDim.x + threadIdx.x;
    // hist (g_cnt zeroed by previous call's scan1; static-zero on first call)
    if (i < NE) atomicAdd(&g_cnt[__ldg(ei + NE + i)], 1);
    // zero stat buffers
    if (i < 128) {
        g_sum0[i] = 0.0; g_sumsq0[i] = 0.0;
        g_sum1[i] = 0.0; g_sumsq1[i] = 0.0;
    }
    // zero output (poisoned by harness each run)
    if (i < NG * HID) out[i] = 0.f;
    // layer-0 message table
    if (i < 76 * 32) {
        int t = i >> 5, lane = i & 31;
        float4 n4 = __ldg((const float4*)(nemb + (t >> 2) * HID) + lane);
        float4 e4 = __ldg((const float4*)(eemb + (t & 3) * HID) + lane);
        float4 m;
        m.x = fmaxf(n4.x + e4.x, 0.f);
        m.y = fmaxf(n4.y + e4.y, 0.f);
        m.z = fmaxf(n4.z + e4.z, 0.f);
        m.w = fmaxf(n4.w + e4.w, 0.f);
        *((float4*)(g_T + t * HID) + lane) = m;
    }
    // fragment-major hi/lo weights
    if (i < 4 * HID * HID) {
        int w = i >> 14;
        int k = (i >> 7) & 127;
        int n = i & 127;
        int l = w >> 1;
        const float* W = (w & 1) ? W2 : W1;
        float v = __ldg(W + l * HID * HID + k * HID + n);
        uint32_t h, lo;
        split_tf32(v, h, lo);
        int lane = (n & 7) * 4 + (k & 3);
        int word = (k >> 2) & 1;
        int base4 = ((w * 256 + (k >> 3) * 16 + (n >> 3)) * 32 + lane) * 4;
        g_Wf[base4 + word] = h;
        g_Wf[base4 + 2 + word] = lo;
    }
}

// ---------------- scan phase 1: per-block exclusive scan + block totals; reset g_cnt ----------------
__global__ void scan1_kernel() {
    __shared__ int sh[SCAN_B];
    int tid = threadIdx.x;
    int i = blockIdx.x * SCAN_B + tid;
    int v = (i < NN) ? g_cnt[i] : 0;
    if (i < NN) g_cnt[i] = 0;          // clean for next call's hist
    sh[tid] = v;
    __syncthreads();
#pragma unroll
    for (int d = 1; d < SCAN_B; d <<= 1) {
        int t = (tid >= d) ? sh[tid - d] : 0;
        __syncthreads();
        sh[tid] += t;
        __syncthreads();
    }
    if (i < NN) g_off[i] = sh[tid] - v;
    if (tid == SCAN_B - 1) g_bsum[blockIdx.x] = sh[tid];
}

// ---------------- scan phase 2: each block scans the 98 totals in smem, adds its prefix ----------------
__global__ void scan3_kernel() {
    __shared__ int sh[128];
    int tid = threadIdx.x;
    if (tid < 128) sh[tid] = (tid < SCAN_BLOCKS) ? g_bsum[tid] : 0;
    __syncthreads();
    if (tid < 128) {
#pragma unroll
        for (int d = 1; d < 128; d <<= 1) {
            int t = (tid >= d) ? sh[tid - d] : 0;
            __syncthreads();
            sh[tid] += t;
            __syncthreads();
        }
    } else {
#pragma unroll
        for (int d = 1; d < 128; d <<= 1) { __syncthreads(); __syncthreads(); }
    }
    int prefix = (blockIdx.x > 0) ? sh[blockIdx.x - 1] : 0;
    int i = blockIdx.x * SCAN_B + tid;
    if (i < NN) {
        int o = g_off[i] + prefix;
        g_off[i] = o;
        g_cur[i] = o;
    }
    if (i == 0) g_off[NN] = NE;
}

// ---------------- scatter both lists with one atomic ----------------
__global__ void scatter_kernel(const int* __restrict__ ei, const int* __restrict__ ea,
                               const int* __restrict__ xi) {
    int e = blockIdx.x * blockDim.x + threadIdx.x;
    if (e >= NE) return;
    int src = __ldg(ei + e);
    int dst = __ldg(ei + NE + e);
    int attr = __ldg(ea + e);
    int p = atomicAdd(&g_cur[dst], 1);
    g_list[p] = (__ldg(xi + src) << 2) | attr;
    g_list2[p] = (src << 2) | attr;
}

// ---------------- aggregate layer 0: M[n] = nemb[xi[n]] + sum g_T[pk] (L1-resident table) ----------------
__global__ void aggregate0_kernel(const int* __restrict__ xi, const float* __restrict__ nemb,
                                  float* __restrict__ M) {
    int node = (blockIdx.x * blockDim.x + threadIdx.x) >> 5;
    int lane = threadIdx.x & 31;
    if (node >= NN) return;
    int s = g_off[node];
    int e = g_off[node + 1];
    float4 acc = __ldg((const float4*)(nemb + (size_t)__ldg(xi + node) * HID) + lane);
    for (int i = s; i < e; i++) {
        int pk = __ldg(g_list + i);
        float4 m = __ldg((const float4*)(g_T + (size_t)pk * HID) + lane);
        acc.x += m.x;
        acc.y += m.y;
        acc.z += m.z;
        acc.w += m.w;
    }
    *((float4*)(M + node * HID) + lane) = acc;
}

// ---------------- aggregate layer 1: inline finalize from S0, serial gather loop ----------------
__global__ void aggregate1_kernel(const float* __restrict__ X, float* __restrict__ M,
                                  const float* __restrict__ eemb,
                                  const float* __restrict__ gw, const float* __restrict__ bw) {
    __shared__ float s_sc[128], s_sh[128];
    int tid = threadIdx.x;
    if (tid < 128) {
        float sc, sh;
        scale_shift(g_sum0, g_sumsq0, gw, bw, tid, sc, sh);
        s_sc[tid] = sc;
        s_sh[tid] = sh;
    }
    __syncthreads();
    int node = (blockIdx.x * blockDim.x + tid) >> 5;
    int lane = tid & 31;
    if (node >= NN) return;
    float4 sc = *(const float4*)(s_sc + lane * 4);
    float4 sh = *(const float4*)(s_sh + lane * 4);
    int s = g_off[node];
    int e = g_off[node + 1];
    float4 acc = __ldg((const float4*)(X + node * HID) + lane);
    acc.x = fmaf(acc.x, sc.x, sh.x);
    acc.y = fmaf(acc.y, sc.y, sh.y);
    acc.z = fmaf(acc.z, sc.z, sh.z);
    acc.w = fmaf(acc.w, sc.w, sh.w);
    for (int i = s; i < e; i++) {
        int pk = __ldg(g_list2 + i);
        int src = pk >> 2, attr = pk & 3;
        float4 x4 = __ldg((const float4*)(X + (size_t)src * HID) + lane);
        float4 e4 = __ldg((const float4*)(eemb + attr * HID) + lane);
        float a, b, c, d;
        a = fmaf(x4.x, sc.x, sh.x) + e4.x;
        b = fmaf(x4.y, sc.y, sh.y) + e4.y;
        c = fmaf(x4.z, sc.z, sh.z) + e4.z;
        d = fmaf(x4.w, sc.w, sh.w) + e4.w;
        acc.x += fmaxf(a, 0.f);
        acc.y += fmaxf(b, 0.f);
        acc.z += fmaxf(c, 0.f);
        acc.w += fmaxf(d, 0.f);
    }
    *((float4*)(M + node * HID) + lane) = acc;
}

// ---------------- fused 3xTF32 double-GEMM: R = relu(relu(M@W1+b1)@W2+b2), stats -> (sum,sumsq) ----------------
#define MTILE 128
#define RS 36
#define RS2 132
#define RAW_WORDS (MTILE * RS)
#define STAT_OFF (2 * RAW_WORDS)
#define AS_OFF (STAT_OFF + 256)
#define SMEM_GEMM ((AS_OFF + MTILE * RS2) * 4)

__global__ void __launch_bounds__(256, 2)
fused_gemm_kernel(const float* __restrict__ M, const uint4* __restrict__ Wf1,
                  const float* __restrict__ b1, const uint4* __restrict__ Wf2,
                  const float* __restrict__ b2, float* __restrict__ R,
                  double* __restrict__ gsum, double* __restrict__ gsumsq) {
    extern __shared__ char smem[];
    float* raw = (float*)smem;
    float* ssum = (float*)smem + STAT_OFF;
    float* ssq = ssum + 128;
    float* As = (float*)smem + AS_OFF;

    uint32_t rawAddr;
    asm("{ .reg .u64 t; cvta.to.shared.u64 t, %1; cvt.u32.u64 %0, t; }"
        : "=r"(rawAddr) : "l"(smem));

    int tid = threadIdx.x, wid = tid >> 5, lane = tid & 31;
    int wm = wid & 3, wn = wid >> 2;
    int g = lane >> 2, tg = lane & 3;
    int rowBase = blockIdx.x * MTILE;

    ssum[tid] = 0.f;

    auto issue_chunk = [&](int chunk, int buf) {
#pragma unroll
        for (int j = 0; j < 4; j++) {
            int i = tid + j * 256;
            int r = i >> 3, q = i & 7;
            int grow = rowBase + r;
            const float* src = M + (size_t)min(grow, NN - 1) * HID + chunk * 32 + q * 4;
            uint32_t dst = rawAddr + (uint32_t)(buf * RAW_WORDS + r * RS + q * 4) * 4u;
            int sz = (grow < NN) ? 16 : 0;
            asm volatile("cp.async.cg.shared.global [%0], [%1], 16, %2;"
                         :: "r"(dst), "l"(src), "r"(sz));
        }
        asm volatile("cp.async.commit_group;");
    };
    issue_chunk(0, 0);
    issue_chunk(1, 1);

    float acc[2][8][4];
#pragma unroll
    for (int mt = 0; mt < 2; mt++)
#pragma unroll
        for (int nt = 0; nt < 8; nt++)
#pragma unroll
            for (int c = 0; c < 4; c++) acc[mt][nt][c] = 0.f;

    // phase 1 mainloop: acc1 = M @ W1
    const uint4* wfw1 = Wf1 + (size_t)(wn * 8) * 32 + lane;
#pragma unroll
    for (int chunk = 0; chunk < 4; chunk++) {
        if (chunk < 3) asm volatile("cp.async.wait_group 1;" ::: "memory");
        else           asm volatile("cp.async.wait_group 0;" ::: "memory");
        __syncthreads();
        const float* rb = raw + (chunk & 1) * RAW_WORDS;

#pragma unroll
        for (int ks = 0; ks < 4; ks++) {
            int k0 = ks * 8;
            int kstep = chunk * 4 + ks;
            const uint4* wfk = wfw1 + (size_t)kstep * 16 * 32;

            uint32_t afH[2][4], afL[2][4];
#pragma unroll
            for (int mt = 0; mt < 2; mt++) {
                int r = wm * 32 + mt * 16 + g;
                float v0 = rb[r * RS + k0 + tg];
                float v1 = rb[(r + 8) * RS + k0 + tg];
                float v2 = rb[r * RS + k0 + tg + 4];
                float v3 = rb[(r + 8) * RS + k0 + tg + 4];
                split_tf32(v0, afH[mt][0], afL[mt][0]);
                split_tf32(v1, afH[mt][1], afL[mt][1]);
                split_tf32(v2, afH[mt][2], afL[mt][2]);
                split_tf32(v3, afH[mt][3], afL[mt][3]);
            }
#pragma unroll
            for (int hb = 0; hb < 2; hb++) {
                uint4 bf[4];
#pragma unroll
                for (int q = 0; q < 4; q++)
                    bf[q] = __ldg(wfk + (hb * 4 + q) * 32);
#pragma unroll
                for (int mt = 0; mt < 2; mt++)
#pragma unroll
                    for (int q = 0; q < 4; q++) {
                        int nt = hb * 4 + q;
                        uint32_t bh[2] = {bf[q].x, bf[q].y};
                        uint32_t bl[2] = {bf[q].z, bf[q].w};
                        MMA_TF32(acc[mt][nt], afH[mt], bl);
                        MMA_TF32(acc[mt][nt], afL[mt], bh);
                        MMA_TF32(acc[mt][nt], afH[mt], bh);
                    }
            }
        }
        __syncthreads();
        if (chunk < 2) issue_chunk(chunk + 2, chunk & 1);
    }

    // phase 1 epilogue: As = relu(acc1 + b1)
#pragma unroll
    for (int nt = 0; nt < 8; nt++) {
        int col = wn * 64 + nt * 8 + tg * 2;
        float2 bv = __ldg((const float2*)(b1 + col));
#pragma unroll
        for (int mt = 0; mt < 2; mt++) {
            int r = wm * 32 + mt * 16 + g;
            float2 oa, ob;
            oa.x = fmaxf(acc[mt][nt][0] + bv.x, 0.f);
            oa.y = fmaxf(acc[mt][nt][1] + bv.y, 0.f);
            ob.x = fmaxf(acc[mt][nt][2] + bv.x, 0.f);
            ob.y = fmaxf(acc[mt][nt][3] + bv.y, 0.f);
            *(float2*)(As + r * RS2 + col) = oa;
            *(float2*)(As + (r + 8) * RS2 + col) = ob;
            acc[mt][nt][0] = 0.f; acc[mt][nt][1] = 0.f;
            acc[mt][nt][2] = 0.f; acc[mt][nt][3] = 0.f;
        }
    }
    __syncthreads();

    // phase 2 mainloop: acc2 = As @ W2
    const uint4* wfw2 = Wf2 + (size_t)(wn * 8) * 32 + lane;
#pragma unroll
    for (int kstep = 0; kstep < 16; kstep++) {
        int k0 = kstep * 8;
        const uint4* wfk = wfw2 + (size_t)kstep * 16 * 32;

        uint32_t afH[2][4], afL[2][4];
#pragma unroll
        for (int mt = 0; mt < 2; mt++) {
            int r = wm * 32 + mt * 16 + g;
            float v0 = As[r * RS2 + k0 + tg];
            float v1 = As[(r + 8) * RS2 + k0 + tg];
            float v2 = As[r * RS2 + k0 + tg + 4];
            float v3 = As[(r + 8) * RS2 + k0 + tg + 4];
            split_tf32(v0, afH[mt][0], afL[mt][0]);
            split_tf32(v1, afH[mt][1], afL[mt][1]);
            split_tf32(v2, afH[mt][2], afL[mt][2]);
            split_tf32(v3, afH[mt][3], afL[mt][3]);
        }
#pragma unroll
        for (int hb = 0; hb < 2; hb++) {
            uint4 bf[4];
#pragma unroll
            for (int q = 0; q < 4; q++)
                bf[q] = __ldg(wfk + (hb * 4 + q) * 32);
#pragma unroll
            for (int mt = 0; mt < 2; mt++)
#pragma unroll
                for (int q = 0; q < 4; q++) {
                    int nt = hb * 4 + q;
                    uint32_t bh[2] = {bf[q].x, bf[q].y};
                    uint32_t bl[2] = {bf[q].z, bf[q].w};
                    MMA_TF32(acc[mt][nt], afH[mt], bl);
                    MMA_TF32(acc[mt][nt], afL[mt], bh);
                    MMA_TF32(acc[mt][nt], afH[mt], bh);
                }
        }
    }

    // phase 2 epilogue: R = relu(acc2 + b2), column stats
#pragma unroll
    for (int nt = 0; nt < 8; nt++) {
        int col = wn * 64 + nt * 8 + tg * 2;
        float2 bv = __ldg((const float2*)(b2 + col));
        float s0 = 0.f, s1 = 0.f, q0 = 0.f, q1 = 0.f;
#pragma unroll
        for (int mt = 0; mt < 2; mt++) {
            int r0 = rowBase + wm * 32 + mt * 16 + g;
            float2 oa, ob;
            oa.x = fmaxf(acc[mt][nt][0] + bv.x, 0.f);
            oa.y = fmaxf(acc[mt][nt][1] + bv.y, 0.f);
            ob.x = fmaxf(acc[mt][nt][2] + bv.x, 0.f);
            ob.y = fmaxf(acc[mt][nt][3] + bv.y, 0.f);
            if (r0 < NN) {
                *(float2*)(R + r0 * HID + col) = oa;
                s0 += oa.x; q0 += oa.x * oa.x; s1 += oa.y; q1 += oa.y * oa.y;
            }
            if (r0 + 8 < NN) {
                *(float2*)(R + (r0 + 8) * HID + col) = ob;
                s0 += ob.x; q0 += ob.x * ob.x; s1 += ob.y; q1 += ob.y * ob.y;
            }
        }
#pragma unroll
        for (int m = 16; m >= 4; m >>= 1) {
            s0 += __shfl_xor_sync(0xffffffff, s0, m);
            s1 += __shfl_xor_sync(0xffffffff, s1, m);
            q0 += __shfl_xor_sync(0xffffffff, q0, m);
            q1 += __shfl_xor_sync(0xffffffff, q1, m);
        }
        if (lane < 4) {
            int c0 = wn * 64 + nt * 8 + lane * 2;
            atomicAdd(&ssum[c0], s0);
            atomicAdd(&ssum[c0 + 1], s1);
            atomicAdd(&ssq[c0], q0);
            atomicAdd(&ssq[c0 + 1], q1);
        }
    }
    __syncthreads();
    if (tid < 128) {
        atomicAdd(&gsum[tid], (double)ssum[tid]);
        atomicAdd(&gsumsq[tid], (double)ssq[tid]);
    }
}

// ---------------- pooling: inline finalize from S1, then segment-add ----------------
__global__ void pool_kernel(const float* __restrict__ R, const int* __restrict__ batch,
                            float* __restrict__ out,
                            const float* __restrict__ gw, const float* __restrict__ bw) {
    __shared__ float s_sc[128], s_sh[128];
    int tid = threadIdx.x;
    if (tid < 128) {
        float sc, sh;
        scale_shift(g_sum1, g_sumsq1, gw, bw, tid, sc, sh);
        s_sc[tid] = sc;
        s_sh[tid] = sh;
    }
    __syncthreads();
    int warp = (blockIdx.x * blockDim.x + tid) >> 5;
    int lane = tid & 31;
    if (warp >= NN) return;
    float4 sc = *(const float4*)(s_sc + lane * 4);
    float4 sh = *(const float4*)(s_sh + lane * 4);
    int g = __ldg(batch + warp);
    float4 v = __ldg((const float4*)(R + warp * HID) + lane);
    v.x = fmaf(v.x, sc.x, sh.x);
    v.y = fmaf(v.y, sc.y, sh.y);
    v.z = fmaf(v.z, sc.z, sh.z);
    v.w = fmaf(v.w, sc.w, sh.w);
    float* p = out + g * HID + lane * 4;
    asm volatile("red.global.add.v4.f32 [%0], {%1,%2,%3,%4};"
                 :: "l"(p), "f"(v.x), "f"(v.y), "f"(v.z), "f"(v.w) : "memory");
}

// ---------------- host ----------------
extern "C" void kernel_launch(void* const* d_in, const int* in_sizes, int n_in,
                              void* d_out, int out_size) {
    const int*   x_idx      = (const int*)d_in[0];
    const int*   edge_index = (const int*)d_in[1];
    const int*   edge_attr  = (const int*)d_in[2];
    const int*   batch      = (const int*)d_in[3];
    const float* node_emb   = (const float*)d_in[4];
    const float* edge_emb   = (const float*)d_in[5];
    const float* W1         = (const float*)d_in[6];
    const float* b1         = (const float*)d_in[7];
    const float* W2         = (const float*)d_in[8];
    const float* b2         = (const float*)d_in[9];
    const float* bn_g       = (const float*)d_in[10];
    const float* bn_b       = (const float*)d_in[11];
    float* out = (float*)d_out;

    cudaFuncSetAttribute(fused_gemm_kernel,
                         cudaFuncAttributeMaxDynamicSharedMemorySize, SMEM_GEMM);

    float *M, *R;
    uint4* Wf;
    double *S0, *Q0, *S1, *Q1;
    cudaGetSymbolAddress((void**)&M, g_M);
    cudaGetSymbolAddress((void**)&R, g_R);
    cudaGetSymbolAddress((void**)&Wf, g_Wf);
    cudaGetSymbolAddress((void**)&S0, g_sum0);
    cudaGetSymbolAddress((void**)&Q0, g_sumsq0);
    cudaGetSymbolAddress((void**)&S1, g_sum1);
    cudaGetSymbolAddress((void**)&Q1, g_sumsq1);

    int gemmBlocks = (NN + MTILE - 1) / MTILE;
    int edgeBlocks = (NE + 255) / 256;
    int nodeWarpBlocks = (NN * 32 + 255) / 256;

    prep_kernel<<<edgeBlocks, 256>>>(W1, W2, node_emb, edge_emb, edge_index, out);
    scan1_kernel<<<SCAN_BLOCKS, SCAN_B>>>();
    scan3_kernel<<<SCAN_BLOCKS, SCAN_B>>>();
    scatter_kernel<<<edgeBlocks, 256>>>(edge_index, edge_attr, x_idx);

    // layer 0
    aggregate0_kernel<<<nodeWarpBlocks, 256>>>(x_idx, node_emb, M);
    fused_gemm_kernel<<<gemmBlocks, 256, SMEM_GEMM>>>(
        M, Wf, b1, Wf + 8192, b2, R, S0, Q0);
    // layer 1
    aggregate1_kernel<<<nodeWarpBlocks, 256>>>(R, M, edge_emb, bn_g, bn_b);
    fused_gemm_kernel<<<gemmBlocks, 256, SMEM_GEMM>>>(
        M, Wf + 16384, b1 + HID, Wf + 24576, b2 + HID, R, S1, Q1);

    pool_kernel<<<nodeWarpBlocks, 256>>>(R, batch, out, bn_g + HID, bn_b + HID);
}

// round 16
// speedup vs baseline: 1.3045x; 1.3045x over previous
#include <cuda_runtime.h>
#include <cstdint>

#define HID 128
#define NN 50000
#define NE 800000
#define NG 64
#define NL 2

#define SCAN_B 512
#define SCAN_BLOCKS ((NN + SCAN_B - 1) / SCAN_B)   // 98

// ---------------- scratch (static device allocations) ----------------
__device__ __align__(16) float g_M[NN * HID];    // x + aggregation (gemm input)
__device__ __align__(16) float g_R[NN * HID];    // layer raw output
__device__ __align__(16) uint32_t g_Wf[4 * 32768]; // fragment-major hi/lo weights
__device__ __align__(16) float g_T[76 * HID];    // layer-0 message table relu(nemb[i]+eemb[a])
__device__ int g_cnt[NN];                        // zeroed by scan1 of the PREVIOUS call
__device__ int g_off[NN + 1];
__device__ int g_cur[NN];
__device__ int g_bsum[SCAN_BLOCKS];
__device__ int g_list[NE];                       // (x_idx[src]<<2)|attr  (layer 0)
__device__ int g_list2[NE];                      // (src<<2)|attr         (layer 1)
__device__ double g_sum0[HID], g_sumsq0[HID];    // layer-0 BN stats
__device__ double g_sum1[HID], g_sumsq1[HID];    // layer-1 BN stats
__device__ __align__(16) float g_scale[HID];
__device__ __align__(16) float g_shift[HID];

__device__ __forceinline__ uint32_t f2tf32(float v) {
    uint32_t o;
    asm("cvt.rna.tf32.f32 %0, %1;" : "=r"(o) : "f"(v));
    return o;
}
__device__ __forceinline__ void split_tf32(float v, uint32_t& h, uint32_t& l) {
    h = f2tf32(v);
    l = f2tf32(v - __uint_as_float(h));
}

#define MMA_TF32(d, a, b) \
    asm volatile("mma.sync.aligned.m16n8k8.row.col.f32.tf32.tf32.f32 " \
        "{%0,%1,%2,%3}, {%4,%5,%6,%7}, {%8,%9}, {%0,%1,%2,%3};" \
        : "+f"((d)[0]), "+f"((d)[1]), "+f"((d)[2]), "+f"((d)[3]) \
        : "r"((a)[0]), "r"((a)[1]), "r"((a)[2]), "r"((a)[3]), \
          "r"((b)[0]), "r"((b)[1]))

// ---------------- prep: weights, msg table, hist, zero stats+out (one kernel) ----------------
__global__ void prep_kernel(const float* __restrict__ W1, const float* __restrict__ W2,
                            const float* __restrict__ nemb, const float* __restrict__ eemb,
                            const int* __restrict__ ei, float* __restrict__ out) {
    int i = blockIdx.x * blockDim.x + threadIdx.x;
    // hist (g_cnt zeroed by previous call's scan1; static-zero on first call)
    if (i < NE) atomicAdd(&g_cnt[__ldg(ei + NE + i)], 1);
    // zero stat buffers
    if (i < 128) {
        g_sum0[i] = 0.0; g_sumsq0[i] = 0.0;
        g_sum1[i] = 0.0; g_sumsq1[i] = 0.0;
    }
    // zero output (poisoned by harness each run)
    if (i < NG * HID) out[i] = 0.f;
    // layer-0 message table
    if (i < 76 * 32) {
        int t = i >> 5, lane = i & 31;
        float4 n4 = __ldg((const float4*)(nemb + (t >> 2) * HID) + lane);
        float4 e4 = __ldg((const float4*)(eemb + (t & 3) * HID) + lane);
        float4 m;
        m.x = fmaxf(n4.x + e4.x, 0.f);
        m.y = fmaxf(n4.y + e4.y, 0.f);
        m.z = fmaxf(n4.z + e4.z, 0.f);
        m.w = fmaxf(n4.w + e4.w, 0.f);
        *((float4*)(g_T + t * HID) + lane) = m;
    }
    // fragment-major hi/lo weights
    if (i < 4 * HID * HID) {
        int w = i >> 14;
        int k = (i >> 7) & 127;
        int n = i & 127;
        int l = w >> 1;
        const float* W = (w & 1) ? W2 : W1;
        float v = __ldg(W + l * HID * HID + k * HID + n);
        uint32_t h, lo;
        split_tf32(v, h, lo);
        int lane = (n & 7) * 4 + (k & 3);
        int word = (k >> 2) & 1;
        int base4 = ((w * 256 + (k >> 3) * 16 + (n >> 3)) * 32 + lane) * 4;
        g_Wf[base4 + word] = h;
        g_Wf[base4 + 2 + word] = lo;
    }
}

// ---------------- scan phase 1: per-block exclusive scan + block totals; reset g_cnt ----------------
__global__ void scan1_kernel() {
    __shared__ int sh[SCAN_B];
    int tid = threadIdx.x;
    int i = blockIdx.x * SCAN_B + tid;
    int v = (i < NN) ? g_cnt[i] : 0;
    if (i < NN) g_cnt[i] = 0;          // clean for next call's hist
    sh[tid] = v;
    __syncthreads();
#pragma unroll
    for (int d = 1; d < SCAN_B; d <<= 1) {
        int t = (tid >= d) ? sh[tid - d] : 0;
        __syncthreads();
        sh[tid] += t;
        __syncthreads();
    }
    if (i < NN) g_off[i] = sh[tid] - v;
    if (tid == SCAN_B - 1) g_bsum[blockIdx.x] = sh[tid];
}

// ---------------- scan phase 2: each block scans the 98 totals in smem, adds its prefix ----------------
__global__ void scan3_kernel() {
    __shared__ int sh[128];
    int tid = threadIdx.x;
    if (tid < 128) sh[tid] = (tid < SCAN_BLOCKS) ? g_bsum[tid] : 0;
    __syncthreads();
    if (tid < 128) {
#pragma unroll
        for (int d = 1; d < 128; d <<= 1) {
            int t = (tid >= d) ? sh[tid - d] : 0;
            __syncthreads();
            sh[tid] += t;
            __syncthreads();
        }
    } else {
#pragma unroll
        for (int d = 1; d < 128; d <<= 1) { __syncthreads(); __syncthreads(); }
    }
    int prefix = (blockIdx.x > 0) ? sh[blockIdx.x - 1] : 0;
    int i = blockIdx.x * SCAN_B + tid;
    if (i < NN) {
        int o = g_off[i] + prefix;
        g_off[i] = o;
        g_cur[i] = o;
    }
    if (i == 0) g_off[NN] = NE;
}

// ---------------- scatter both lists with one atomic ----------------
__global__ void scatter_kernel(const int* __restrict__ ei, const int* __restrict__ ea,
                               const int* __restrict__ xi) {
    int e = blockIdx.x * blockDim.x + threadIdx.x;
    if (e >= NE) return;
    int src = __ldg(ei + e);
    int dst = __ldg(ei + NE + e);
    int attr = __ldg(ea + e);
    int p = atomicAdd(&g_cur[dst], 1);
    g_list[p] = (__ldg(xi + src) << 2) | attr;
    g_list2[p] = (src << 2) | attr;
}

// ---------------- aggregate layer 0: M[n] = nemb[xi[n]] + sum g_T[pk] (L1-resident table) ----------------
__global__ void aggregate0_kernel(const int* __restrict__ xi, const float* __restrict__ nemb,
                                  float* __restrict__ M) {
    int node = (blockIdx.x * blockDim.x + threadIdx.x) >> 5;
    int lane = threadIdx.x & 31;
    if (node >= NN) return;
    int s = g_off[node];
    int e = g_off[node + 1];
    float4 acc = __ldg((const float4*)(nemb + (size_t)__ldg(xi + node) * HID) + lane);
    for (int i = s; i < e; i++) {
        int pk = __ldg(g_list + i);
        float4 m = __ldg((const float4*)(g_T + (size_t)pk * HID) + lane);
        acc.x += m.x;
        acc.y += m.y;
        acc.z += m.z;
        acc.w += m.w;
    }
    *((float4*)(M + node * HID) + lane) = acc;
}

// ---------------- finalize: g_scale/g_shift from a stat pair (one tiny launch per layer) ----------------
__global__ void finalize_kernel(const double* __restrict__ sum, const double* __restrict__ sumsq,
                                const float* __restrict__ gw, const float* __restrict__ bw) {
    int c = threadIdx.x;
    double mu = sum[c] / (double)NN;
    double var = sumsq[c] / (double)NN - mu * mu;
    float sc = (float)((double)gw[c] * rsqrt(var + 1e-5));
    g_scale[c] = sc;
    g_shift[c] = bw[c] - (float)mu * sc;
}

// ---------------- aggregate layer 1: norm applied inline from precomputed scale/shift ----------------
__global__ void aggregate1_kernel(const float* __restrict__ X, float* __restrict__ M,
                                  const float* __restrict__ eemb) {
    int node = (blockIdx.x * blockDim.x + threadIdx.x) >> 5;
    int lane = threadIdx.x & 31;
    if (node >= NN) return;
    float4 sc = *(const float4*)(g_scale + lane * 4);
    float4 sh = *(const float4*)(g_shift + lane * 4);
    int s = g_off[node];
    int e = g_off[node + 1];
    float4 acc = __ldg((const float4*)(X + node * HID) + lane);
    acc.x = fmaf(acc.x, sc.x, sh.x);
    acc.y = fmaf(acc.y, sc.y, sh.y);
    acc.z = fmaf(acc.z, sc.z, sh.z);
    acc.w = fmaf(acc.w, sc.w, sh.w);
    for (int i = s; i < e; i++) {
        int pk = __ldg(g_list2 + i);
        int src = pk >> 2, attr = pk & 3;
        float4 x4 = __ldg((const float4*)(X + (size_t)src * HID) + lane);
        float4 e4 = __ldg((const float4*)(eemb + attr * HID) + lane);
        float a, b, c, d;
        a = fmaf(x4.x, sc.x, sh.x) + e4.x;
        b = fmaf(x4.y, sc.y, sh.y) + e4.y;
        c = fmaf(x4.z, sc.z, sh.z) + e4.z;
        d = fmaf(x4.w, sc.w, sh.w) + e4.w;
        acc.x += fmaxf(a, 0.f);
        acc.y += fmaxf(b, 0.f);
        acc.z += fmaxf(c, 0.f);
        acc.w += fmaxf(d, 0.f);
    }
    *((float4*)(M + node * HID) + lane) = acc;
}

// ---------------- fused 3xTF32 double-GEMM: R = relu(relu(M@W1+b1)@W2+b2), stats -> (sum,sumsq) ----------------
#define MTILE 128
#define RS 36
#define RS2 132
#define RAW_WORDS (MTILE * RS)
#define STAT_OFF (2 * RAW_WORDS)
#define AS_OFF (STAT_OFF + 256)
#define SMEM_GEMM ((AS_OFF + MTILE * RS2) * 4)

__global__ void __launch_bounds__(256, 2)
fused_gemm_kernel(const float* __restrict__ M, const uint4* __restrict__ Wf1,
                  const float* __restrict__ b1, const uint4* __restrict__ Wf2,
                  const float* __restrict__ b2, float* __restrict__ R,
                  double* __restrict__ gsum, double* __restrict__ gsumsq) {
    extern __shared__ char smem[];
    float* raw = (float*)smem;
    float* ssum = (float*)smem + STAT_OFF;
    float* ssq = ssum + 128;
    float* As = (float*)smem + AS_OFF;

    uint32_t rawAddr;
    asm("{ .reg .u64 t; cvta.to.shared.u64 t, %1; cvt.u32.u64 %0, t; }"
        : "=r"(rawAddr) : "l"(smem));

    int tid = threadIdx.x, wid = tid >> 5, lane = tid & 31;
    int wm = wid & 3, wn = wid >> 2;
    int g = lane >> 2, tg = lane & 3;
    int rowBase = blockIdx.x * MTILE;

    ssum[tid] = 0.f;

    auto issue_chunk = [&](int chunk, int buf) {
#pragma unroll
        for (int j = 0; j < 4; j++) {
            int i = tid + j * 256;
            int r = i >> 3, q = i & 7;
            int grow = rowBase + r;
            const float* src = M + (size_t)min(grow, NN - 1) * HID + chunk * 32 + q * 4;
            uint32_t dst = rawAddr + (uint32_t)(buf * RAW_WORDS + r * RS + q * 4) * 4u;
            int sz = (grow < NN) ? 16 : 0;
            asm volatile("cp.async.cg.shared.global [%0], [%1], 16, %2;"
                         :: "r"(dst), "l"(src), "r"(sz));
        }
        asm volatile("cp.async.commit_group;");
    };
    issue_chunk(0, 0);
    issue_chunk(1, 1);

    float acc[2][8][4];
#pragma unroll
    for (int mt = 0; mt < 2; mt++)
#pragma unroll
        for (int nt = 0; nt < 8; nt++)
#pragma unroll
            for (int c = 0; c < 4; c++) acc[mt][nt][c] = 0.f;

    // phase 1 mainloop: acc1 = M @ W1
    const uint4* wfw1 = Wf1 + (size_t)(wn * 8) * 32 + lane;
#pragma unroll
    for (int chunk = 0; chunk < 4; chunk++) {
        if (chunk < 3) asm volatile("cp.async.wait_group 1;" ::: "memory");
        else           asm volatile("cp.async.wait_group 0;" ::: "memory");
        __syncthreads();
        const float* rb = raw + (chunk & 1) * RAW_WORDS;

#pragma unroll
        for (int ks = 0; ks < 4; ks++) {
            int k0 = ks * 8;
            int kstep = chunk * 4 + ks;
            const uint4* wfk = wfw1 + (size_t)kstep * 16 * 32;

            uint32_t afH[2][4], afL[2][4];
#pragma unroll
            for (int mt = 0; mt < 2; mt++) {
                int r = wm * 32 + mt * 16 + g;
                float v0 = rb[r * RS + k0 + tg];
                float v1 = rb[(r + 8) * RS + k0 + tg];
                float v2 = rb[r * RS + k0 + tg + 4];
                float v3 = rb[(r + 8) * RS + k0 + tg + 4];
                split_tf32(v0, afH[mt][0], afL[mt][0]);
                split_tf32(v1, afH[mt][1], afL[mt][1]);
                split_tf32(v2, afH[mt][2], afL[mt][2]);
                split_tf32(v3, afH[mt][3], afL[mt][3]);
            }
#pragma unroll
            for (int hb = 0; hb < 2; hb++) {
                uint4 bf[4];
#pragma unroll
                for (int q = 0; q < 4; q++)
                    bf[q] = __ldg(wfk + (hb * 4 + q) * 32);
#pragma unroll
                for (int mt = 0; mt < 2; mt++)
#pragma unroll
                    for (int q = 0; q < 4; q++) {
                        int nt = hb * 4 + q;
                        uint32_t bh[2] = {bf[q].x, bf[q].y};
                        uint32_t bl[2] = {bf[q].z, bf[q].w};
                        MMA_TF32(acc[mt][nt], afH[mt], bl);
                        MMA_TF32(acc[mt][nt], afL[mt], bh);
                        MMA_TF32(acc[mt][nt], afH[mt], bh);
                    }
            }
        }
        __syncthreads();
        if (chunk < 2) issue_chunk(chunk + 2, chunk & 1);
    }

    // phase 1 epilogue: As = relu(acc1 + b1)
#pragma unroll
    for (int nt = 0; nt < 8; nt++) {
        int col = wn * 64 + nt * 8 + tg * 2;
        float2 bv = __ldg((const float2*)(b1 + col));
#pragma unroll
        for (int mt = 0; mt < 2; mt++) {
            int r = wm * 32 + mt * 16 + g;
            float2 oa, ob;
            oa.x = fmaxf(acc[mt][nt][0] + bv.x, 0.f);
            oa.y = fmaxf(acc[mt][nt][1] + bv.y, 0.f);
            ob.x = fmaxf(acc[mt][nt][2] + bv.x, 0.f);
            ob.y = fmaxf(acc[mt][nt][3] + bv.y, 0.f);
            *(float2*)(As + r * RS2 + col) = oa;
            *(float2*)(As + (r + 8) * RS2 + col) = ob;
            acc[mt][nt][0] = 0.f; acc[mt][nt][1] = 0.f;
            acc[mt][nt][2] = 0.f; acc[mt][nt][3] = 0.f;
        }
    }
    __syncthreads();

    // phase 2 mainloop: acc2 = As @ W2
    const uint4* wfw2 = Wf2 + (size_t)(wn * 8) * 32 + lane;
#pragma unroll
    for (int kstep = 0; kstep < 16; kstep++) {
        int k0 = kstep * 8;
        const uint4* wfk = wfw2 + (size_t)kstep * 16 * 32;

        uint32_t afH[2][4], afL[2][4];
#pragma unroll
        for (int mt = 0; mt < 2; mt++) {
            int r = wm * 32 + mt * 16 + g;
            float v0 = As[r * RS2 + k0 + tg];
            float v1 = As[(r + 8) * RS2 + k0 + tg];
            float v2 = As[r * RS2 + k0 + tg + 4];
            float v3 = As[(r + 8) * RS2 + k0 + tg + 4];
            split_tf32(v0, afH[mt][0], afL[mt][0]);
            split_tf32(v1, afH[mt][1], afL[mt][1]);
            split_tf32(v2, afH[mt][2], afL[mt][2]);
            split_tf32(v3, afH[mt][3], afL[mt][3]);
        }
#pragma unroll
        for (int hb = 0; hb < 2; hb++) {
            uint4 bf[4];
#pragma unroll
            for (int q = 0; q < 4; q++)
                bf[q] = __ldg(wfk + (hb * 4 + q) * 32);
#pragma unroll
            for (int mt = 0; mt < 2; mt++)
#pragma unroll
                for (int q = 0; q < 4; q++) {
                    int nt = hb * 4 + q;
                    uint32_t bh[2] = {bf[q].x, bf[q].y};
                    uint32_t bl[2] = {bf[q].z, bf[q].w};
                    MMA_TF32(acc[mt][nt], afH[mt], bl);
                    MMA_TF32(acc[mt][nt], afL[mt], bh);
                    MMA_TF32(acc[mt][nt], afH[mt], bh);
                }
        }
    }

    // phase 2 epilogue: R = relu(acc2 + b2), column stats
#pragma unroll
    for (int nt = 0; nt < 8; nt++) {
        int col = wn * 64 + nt * 8 + tg * 2;
        float2 bv = __ldg((const float2*)(b2 + col));
        float s0 = 0.f, s1 = 0.f, q0 = 0.f, q1 = 0.f;
#pragma unroll
        for (int mt = 0; mt < 2; mt++) {
            int r0 = rowBase + wm * 32 + mt * 16 + g;
            float2 oa, ob;
            oa.x = fmaxf(acc[mt][nt][0] + bv.x, 0.f);
            oa.y = fmaxf(acc[mt][nt][1] + bv.y, 0.f);
            ob.x = fmaxf(acc[mt][nt][2] + bv.x, 0.f);
            ob.y = fmaxf(acc[mt][nt][3] + bv.y, 0.f);
            if (r0 < NN) {
                *(float2*)(R + r0 * HID + col) = oa;
                s0 += oa.x; q0 += oa.x * oa.x; s1 += oa.y; q1 += oa.y * oa.y;
            }
            if (r0 + 8 < NN) {
                *(float2*)(R + (r0 + 8) * HID + col) = ob;
                s0 += ob.x; q0 += ob.x * ob.x; s1 += ob.y; q1 += ob.y * ob.y;
            }
        }
#pragma unroll
        for (int m = 16; m >= 4; m >>= 1) {
            s0 += __shfl_xor_sync(0xffffffff, s0, m);
            s1 += __shfl_xor_sync(0xffffffff, s1, m);
            q0 += __shfl_xor_sync(0xffffffff, q0, m);
            q1 += __shfl_xor_sync(0xffffffff, q1, m);
        }
        if (lane < 4) {
            int c0 = wn * 64 + nt * 8 + lane * 2;
            atomicAdd(&ssum[c0], s0);
            atomicAdd(&ssum[c0 + 1], s1);
            atomicAdd(&ssq[c0], q0);
            atomicAdd(&ssq[c0 + 1], q1);
        }
    }
    __syncthreads();
    if (tid < 128) {
        atomicAdd(&gsum[tid], (double)ssum[tid]);
        atomicAdd(&gsumsq[tid], (double)ssq[tid]);
    }
}

// ---------------- pooling: reads precomputed scale/shift ----------------
__global__ void pool_kernel(const float* __restrict__ R, const int* __restrict__ batch,
                            float* __restrict__ out) {
    int warp = (blockIdx.x * blockDim.x + threadIdx.x) >> 5;
    int lane = threadIdx.x & 31;
    if (warp >= NN) return;
    float4 sc = *(const float4*)(g_scale + lane * 4);
    float4 sh = *(const float4*)(g_shift + lane * 4);
    int g = __ldg(batch + warp);
    float4 v = __ldg((const float4*)(R + warp * HID) + lane);
    v.x = fmaf(v.x, sc.x, sh.x);
    v.y = fmaf(v.y, sc.y, sh.y);
    v.z = fmaf(v.z, sc.z, sh.z);
    v.w = fmaf(v.w, sc.w, sh.w);
    float* p = out + g * HID + lane * 4;
    asm volatile("red.global.add.v4.f32 [%0], {%1,%2,%3,%4};"
                 :: "l"(p), "f"(v.x), "f"(v.y), "f"(v.z), "f"(v.w) : "memory");
}

// ---------------- host ----------------
extern "C" void kernel_launch(void* const* d_in, const int* in_sizes, int n_in,
                              void* d_out, int out_size) {
    const int*   x_idx      = (const int*)d_in[0];
    const int*   edge_index = (const int*)d_in[1];
    const int*   edge_attr  = (const int*)d_in[2];
    const int*   batch      = (const int*)d_in[3];
    const float* node_emb   = (const float*)d_in[4];
    const float* edge_emb   = (const float*)d_in[5];
    const float* W1         = (const float*)d_in[6];
    const float* b1         = (const float*)d_in[7];
    const float* W2         = (const float*)d_in[8];
    const float* b2         = (const float*)d_in[9];
    const float* bn_g       = (const float*)d_in[10];
    const float* bn_b       = (const float*)d_in[11];
    float* out = (float*)d_out;

    cudaFuncSetAttribute(fused_gemm_kernel,
                         cudaFuncAttributeMaxDynamicSharedMemorySize, SMEM_GEMM);

    float *M, *R;
    uint4* Wf;
    double *S0, *Q0, *S1, *Q1;
    cudaGetSymbolAddress((void**)&M, g_M);
    cudaGetSymbolAddress((void**)&R, g_R);
    cudaGetSymbolAddress((void**)&Wf, g_Wf);
    cudaGetSymbolAddress((void**)&S0, g_sum0);
    cudaGetSymbolAddress((void**)&Q0, g_sumsq0);
    cudaGetSymbolAddress((void**)&S1, g_sum1);
    cudaGetSymbolAddress((void**)&Q1, g_sumsq1);

    int gemmBlocks = (NN + MTILE - 1) / MTILE;
    int edgeBlocks = (NE + 255) / 256;
    int nodeWarpBlocks = (NN * 32 + 255) / 256;

    prep_kernel<<<edgeBlocks, 256>>>(W1, W2, node_emb, edge_emb, edge_index, out);
    scan1_kernel<<<SCAN_BLOCKS, SCAN_B>>>();
    scan3_kernel<<<SCAN_BLOCKS, SCAN_B>>>();
    scatter_kernel<<<edgeBlocks, 256>>>(edge_index, edge_attr, x_idx);

    // layer 0
    aggregate0_kernel<<<nodeWarpBlocks, 256>>>(x_idx, node_emb, M);
    fused_gemm_kernel<<<gemmBlocks, 256, SMEM_GEMM>>>(
        M, Wf, b1, Wf + 8192, b2, R, S0, Q0);
    finalize_kernel<<<1, 128>>>(S0, Q0, bn_g, bn_b);
    // layer 1
    aggregate1_kernel<<<nodeWarpBlocks, 256>>>(R, M, edge_emb);
    fused_gemm_kernel<<<gemmBlocks, 256, SMEM_GEMM>>>(
        M, Wf + 16384, b1 + HID, Wf + 24576, b2 + HID, R, S1, Q1);
    finalize_kernel<<<1, 128>>>(S1, Q1, bn_g + HID, bn_b + HID);

    pool_kernel<<<nodeWarpBlocks, 256>>>(R, batch, out);
}